// round 11
// baseline (speedup 1.0000x reference)
#include <cuda_runtime.h>
#include <cuda_fp16.h>
#include <math.h>
#include <stdint.h>

// B=2, T=2048, D=3584, N=16, K=8, H=256, WINDOW=1024, SOFT_CAP=50, SCALAR=0.0625

// ---------------- scratch (allocation-free device globals) -------------------
__device__ unsigned short g_Xh  [4096u * 3584u];  // x fp16
__device__ unsigned short g_Wth [8192u * 3584u];  // qkv weight [j][d] K-major fp16
__device__ unsigned short g_OWth[3584u * 4096u];  // o_w^T [d][j] K-major fp16
__device__ unsigned short g_QKVh[4096u * 8192u];  // [B*T][ q | k | v ] fp16
__device__ unsigned short g_ENCh[4096u * 4096u];  // attention output fp16

// ---------------- helpers -----------------------------------------------------
__device__ __forceinline__ uint32_t smem_u32(const void* p) {
    uint32_t a;
    asm("{ .reg .u64 t; cvta.to.shared.u64 t, %1; cvt.u32.u64 %0, t; }" : "=r"(a) : "l"(p));
    return a;
}
__device__ __forceinline__ void ldsm4(uint32_t* d, uint32_t addr) {
    asm volatile("ldmatrix.sync.aligned.m8n8.x4.shared.b16 {%0,%1,%2,%3}, [%4];"
                 : "=r"(d[0]), "=r"(d[1]), "=r"(d[2]), "=r"(d[3]) : "r"(addr));
}
__device__ __forceinline__ void ldsm4t(uint32_t* d, uint32_t addr) {
    asm volatile("ldmatrix.sync.aligned.m8n8.x4.trans.shared.b16 {%0,%1,%2,%3}, [%4];"
                 : "=r"(d[0]), "=r"(d[1]), "=r"(d[2]), "=r"(d[3]) : "r"(addr));
}
__device__ __forceinline__ void mma16816(float* c, const uint32_t* a, uint32_t b0, uint32_t b1) {
    asm volatile("mma.sync.aligned.m16n8k16.row.col.f32.f16.f16.f32 "
                 "{%0,%1,%2,%3}, {%4,%5,%6,%7}, {%8,%9}, {%0,%1,%2,%3};"
                 : "+f"(c[0]), "+f"(c[1]), "+f"(c[2]), "+f"(c[3])
                 : "r"(a[0]), "r"(a[1]), "r"(a[2]), "r"(a[3]), "r"(b0), "r"(b1));
}
__device__ __forceinline__ uint32_t f22u(float a, float b) {
    __half2 h = __floats2half2_rn(a, b);
    return *(uint32_t*)&h;
}
__device__ __forceinline__ void cpa16(uint32_t dst, const void* src) {
    asm volatile("cp.async.cg.shared.global [%0], [%1], 16;" :: "r"(dst), "l"(src));
}

// ---------------- fused prep: conv_x + pack_wt + pack_owt in ONE launch -------
__global__ __launch_bounds__(256) void prep_all(const float* __restrict__ x,
                                                const float* __restrict__ qw,
                                                const float* __restrict__ kvw,
                                                const float* __restrict__ ow)
{
    __shared__ float t[32][33];
    const int blk = blockIdx.x;
    const int c  = threadIdx.x & 31;
    const int r0 = threadIdx.x >> 5;

    if (blk < 14336) {
        size_t i = ((size_t)blk * 256 + threadIdx.x) * 4;
        float4 v = *(const float4*)(x + i);
        uint2 u = make_uint2(f22u(v.x, v.y), f22u(v.z, v.w));
        *(uint2*)((__half*)g_Xh + i) = u;
    } else if (blk < 43008) {
        int lin = blk - 14336;
        int hd  = lin / 896;
        int rem = lin - hd * 896;
        int h0  = (rem / 112) << 5;
        int d0  = (rem % 112) << 5;
        const float* src = (hd < 16) ? (qw + (size_t)hd * 3584 * 256)
                                     : (kvw + (size_t)(hd - 16) * 3584 * 256);
#pragma unroll
        for (int r = r0; r < 32; r += 8)
            t[r][c] = src[(size_t)(d0 + r) * 256 + h0 + c];
        __syncthreads();
#pragma unroll
        for (int r = r0; r < 32; r += 8)
            g_Wth[(size_t)(hd * 256 + h0 + r) * 3584 + d0 + c] =
                __half_as_ushort(__float2half(t[c][r]));
    } else {
        int lin = blk - 43008;
        int j0  = (lin % 128) << 5;
        int d0  = (lin / 128) << 5;
#pragma unroll
        for (int r = r0; r < 32; r += 8)
            t[r][c] = ow[(size_t)(j0 + r) * 3584 + d0 + c];
        __syncthreads();
#pragma unroll
        for (int r = r0; r < 32; r += 8)
            g_OWth[(size_t)(d0 + r) * 4096 + j0 + c] =
                __half_as_ushort(__float2half(t[c][r]));
    }
}

// ------ fp16 HMMA GEMM: R8 config (CTA 128x128, warp 32x64), 5-stage pipeline --
#define PITCH 40
#define STAGE_B 20480
#define NSTG 5
#define HGEMM_SMEM (NSTG * STAGE_B)      // 102400 B -> 2 CTAs/SM

template <typename CT>
__global__ __launch_bounds__(256, 2) void hgemm(const __half* __restrict__ A,
                                                const __half* __restrict__ B,
                                                CT* __restrict__ C,
                                                int Nout, int Kdim)
{
    extern __shared__ __half hsm[];

    const int tid  = threadIdx.x;
    const int lane = tid & 31;
    const int wid  = tid >> 5;
    const int wm = (wid & 3) << 5;
    const int wn = (wid >> 2) << 6;
    const int m0 = blockIdx.y << 7;
    const int n0 = blockIdx.x << 7;
    const int nk = Kdim >> 5;

    const int lrow = tid >> 1;
    const int lcol = (tid & 1) << 4;
    const __half* ag = A + (size_t)(m0 + lrow) * Kdim + lcol;
    const __half* bg = B + (size_t)(n0 + lrow) * Kdim + lcol;

    uint32_t sb  = smem_u32(hsm);
    uint32_t sa  = sb + (uint32_t)(lrow * PITCH + lcol) * 2;
    uint32_t sbq = sa + 10240;

    const uint32_t lq = lane & 15;
    const uint32_t lh = (lane >> 4) << 4;
    uint32_t abase = sb + ((wm + lq) * PITCH) * 2 + lh;
    uint32_t bbase = sb + 10240 + ((wn + lq) * PITCH) * 2 + lh;

    float acc[2][8][4];
#pragma unroll
    for (int i = 0; i < 2; i++)
#pragma unroll
        for (int j = 0; j < 8; j++)
#pragma unroll
            for (int q = 0; q < 4; q++) acc[i][j][q] = 0.f;

#define HLOAD(i, s) do {                                                          \
    uint32_t _da = sa + (uint32_t)(s) * STAGE_B;                                  \
    uint32_t _db = sbq + (uint32_t)(s) * STAGE_B;                                 \
    const __half* _a = ag + ((i) << 5);                                           \
    const __half* _b = bg + ((i) << 5);                                           \
    asm volatile("cp.async.cg.shared.global [%0], [%1], 16;\n\t"                  \
                 "cp.async.cg.shared.global [%2], [%3], 16;\n\t"                  \
                 "cp.async.cg.shared.global [%4], [%5], 16;\n\t"                  \
                 "cp.async.cg.shared.global [%6], [%7], 16;\n\t"                  \
                 "cp.async.commit_group;"                                         \
                 :: "r"(_da), "l"(_a), "r"(_da + 16), "l"(_a + 8),                \
                    "r"(_db), "l"(_b), "r"(_db + 16), "l"(_b + 8));               \
} while (0)

    HLOAD(0, 0);
    HLOAD(1, 1);
    HLOAD(2, 2);
    HLOAD(3, 3);

    for (int i = 0; i < nk; i++) {
        // group i was committed 4 iterations earlier; exact tail chain
        if (i < nk - 3)       asm volatile("cp.async.wait_group 3;");
        else if (i == nk - 3) asm volatile("cp.async.wait_group 2;");
        else if (i == nk - 2) asm volatile("cp.async.wait_group 1;");
        else                  asm volatile("cp.async.wait_group 0;");
        __syncthreads();
        if (i + 4 < nk) HLOAD(i + 4, (i + 4) % NSTG);   // slot (i-1)%5, safe after sync

        uint32_t so = (uint32_t)(i % NSTG) * STAGE_B;
        uint32_t ab = abase + so;
        uint32_t bb = bbase + so;
#pragma unroll
        for (int ks = 0; ks < 2; ks++) {
            uint32_t af[2][4], bf[4][4];
            ldsm4(af[0], ab + ks * 32);
            ldsm4(af[1], ab + 16 * PITCH * 2 + ks * 32);
#pragma unroll
            for (int p = 0; p < 4; p++)
                ldsm4(bf[p], bb + p * (16 * PITCH * 2) + ks * 32);
#pragma unroll
            for (int mt = 0; mt < 2; mt++)
#pragma unroll
                for (int p = 0; p < 4; p++) {
                    mma16816(acc[mt][2 * p],     af[mt], bf[p][0], bf[p][2]);
                    mma16816(acc[mt][2 * p + 1], af[mt], bf[p][1], bf[p][3]);
                }
        }
    }

    const int g  = lane >> 2;
    const int cc = (lane & 3) << 1;
#pragma unroll
    for (int mt = 0; mt < 2; mt++) {
        int r = m0 + wm + mt * 16 + g;
#pragma unroll
        for (int nt = 0; nt < 8; nt++) {
            size_t off = (size_t)r * Nout + n0 + wn + nt * 8 + cc;
            if (sizeof(CT) == 2) {
                __half* cp = (__half*)C + off;
                *(uint32_t*)cp = f22u(acc[mt][nt][0], acc[mt][nt][1]);
                *(uint32_t*)(cp + (size_t)8 * Nout) = f22u(acc[mt][nt][2], acc[mt][nt][3]);
            } else {
                float* cp = (float*)C + off;
                *(float2*)cp = make_float2(acc[mt][nt][0], acc[mt][nt][1]);
                *(float2*)(cp + (size_t)8 * Nout) = make_float2(acc[mt][nt][2], acc[mt][nt][3]);
            }
        }
    }
}

// ---------------- RoPE (+ q scaling), in place on fp16 QKV --------------------
__global__ __launch_bounds__(128) void rope_kernel(const int* __restrict__ segpos)
{
    int bt = blockIdx.x;
    int hh = blockIdx.y;
    int i  = threadIdx.x;
    __half* p = (__half*)g_QKVh + (size_t)bt * 8192 + hh * 256;
    float pos = (float)segpos[bt];
    float ts  = powf(10000.0f, (float)i * (1.0f / 128.0f));
    float ang = pos / ts;
    float s, c;
    sincosf(ang, &s, &c);
    float a  = __half2float(p[i]);
    float b2 = __half2float(p[i + 128]);
    float o1 = a * c - b2 * s;
    float o2 = b2 * c + a * s;
    if (hh < 16) { o1 *= 0.0625f; o2 *= 0.0625f; }
    p[i]       = __float2half(o1);
    p[i + 128] = __float2half(o2);
}

// ---------------- fp16 tensor-core flash attention ----------------------------
// Heavy-first ordering + interior-chunk fast path (mask math skipped when the
// whole warp x chunk block is inside the causal window).
#define APITCH 264
#define KS_OFF (128 * APITCH)
#define KS_SZ  (64 * APITCH)
#define VS_OFF (KS_OFF + 2 * KS_SZ)
#define ATTN_SMEM ((KS_OFF + 4 * KS_SZ) * 2)   // 202752 bytes

__global__ __launch_bounds__(256, 1) void attn_kernel()
{
    extern __shared__ __half ash[];
    const int tid  = threadIdx.x;
    const int lane = tid & 31;
    const int w    = tid >> 5;
    const int t0   = (15 - blockIdx.x) << 7;   // heavy tiles scheduled first
    const int n    = blockIdx.y;
    const int b    = blockIdx.z;
    const int kh   = n >> 1;
    uint32_t sb = smem_u32(ash);

    const __half* qkvh = (const __half*)g_QKVh + (size_t)b * 2048 * 8192;

    {
        const __half* qs = qkvh + (size_t)t0 * 8192 + n * 256;
#pragma unroll
        for (int it = 0; it < 16; it++) {
            int slot = it * 256 + tid;
            int r = slot >> 5, cs = (slot & 31) << 3;
            cpa16(sb + (r * APITCH + cs) * 2, qs + (size_t)r * 8192 + cs);
        }
    }

    int smin = t0 - 1023; if (smin < 0) smin = 0;
    const int c0 = smin >> 6, c1 = (t0 + 127) >> 6;

    const int ldr = tid >> 5, ldc = (tid & 31) << 3;

#define LOADKV(sg0, bf) do {                                                       \
    const __half* _ks = qkvh + (size_t)(sg0) * 8192 + 4096 + kh * 256;             \
    uint32_t _kb = sb + (KS_OFF + (bf) * KS_SZ) * 2;                               \
    uint32_t _vb = sb + (VS_OFF + (bf) * KS_SZ) * 2;                               \
    _Pragma("unroll")                                                              \
    for (int _it = 0; _it < 8; _it++) {                                            \
        int _r = _it * 8 + ldr;                                                    \
        cpa16(_kb + (_r * APITCH + ldc) * 2, _ks + (size_t)_r * 8192 + ldc);       \
        cpa16(_vb + (_r * APITCH + ldc) * 2, _ks + (size_t)_r * 8192 + 2048 + ldc);\
    }                                                                              \
    asm volatile("cp.async.commit_group;");                                        \
} while (0)

    LOADKV(c0 << 6, 0);

    float of[32][4];
#pragma unroll
    for (int f = 0; f < 32; f++)
#pragma unroll
        for (int q = 0; q < 4; q++) of[f][q] = 0.f;
    float m0 = -1e30f, m1 = -1e30f, l0 = 0.f, l1 = 0.f;

    const uint32_t lq  = lane & 15;
    const uint32_t lh16 = (lane >> 4) << 4;
    uint32_t qb  = sb + (((w << 4) + lq) * APITCH) * 2 + lh16;
    uint32_t kvl = (lq * APITCH) * 2 + lh16;

    const int row0 = t0 + (w << 4) + (lane >> 2);
    const int row1 = row0 + 8;
    const int colq = (lane & 3) << 1;
    const int wr0 = t0 + (w << 4), wr1 = wr0 + 15;

    int buf = 0;
    for (int c = c0; c <= c1; c++) {
        const int sg0 = c << 6;
        if (c < c1) {
            LOADKV((c + 1) << 6, buf ^ 1);
            asm volatile("cp.async.wait_group 1;");
        } else {
            asm volatile("cp.async.wait_group 0;");
        }
        __syncthreads();

        if (sg0 <= wr1 && sg0 + 63 >= wr0 - 1023) {
            uint32_t kb = sb + (KS_OFF + buf * KS_SZ) * 2 + kvl;
            uint32_t vb = sb + (VS_OFF + buf * KS_SZ) * 2 + kvl;

            float sf[8][4];
#pragma unroll
            for (int j = 0; j < 8; j++)
#pragma unroll
                for (int q = 0; q < 4; q++) sf[j][q] = 0.f;

#pragma unroll
            for (int kk = 0; kk < 16; kk++) {
                uint32_t a[4];
                ldsm4(a, qb + kk * 32);
#pragma unroll
                for (int ng = 0; ng < 4; ng++) {
                    uint32_t bfr[4];
                    ldsm4(bfr, kb + ng * (16 * APITCH * 2) + kk * 32);
                    mma16816(sf[ng * 2],     a, bfr[0], bfr[2]);
                    mma16816(sf[ng * 2 + 1], a, bfr[1], bfr[3]);
                }
            }

            // soft cap + (conditional) window mask — warp-uniform fast path
            float mx0 = -1e30f, mx1 = -1e30f;
            const bool interior = (sg0 + 63 <= wr0) && (sg0 >= wr1 - 1023);
            if (interior) {
#pragma unroll
                for (int j = 0; j < 8; j++) {
#pragma unroll
                    for (int q = 0; q < 4; q++) {
                        float e = __expf(sf[j][q] * 0.04f);
                        sf[j][q] = 50.f * __fdividef(e - 1.f, e + 1.f);
                    }
                    mx0 = fmaxf(mx0, fmaxf(sf[j][0], sf[j][1]));
                    mx1 = fmaxf(mx1, fmaxf(sf[j][2], sf[j][3]));
                }
            } else {
#pragma unroll
                for (int j = 0; j < 8; j++) {
                    int col = sg0 + j * 8 + colq;
#pragma unroll
                    for (int q = 0; q < 4; q++) {
                        float e = __expf(sf[j][q] * 0.04f);
                        float s = 50.f * __fdividef(e - 1.f, e + 1.f);
                        int rr = (q < 2) ? row0 : row1;
                        int cc2 = col + (q & 1);
                        bool ok = (cc2 <= rr) && (cc2 >= rr - 1023);
                        sf[j][q] = ok ? s : -1e30f;
                    }
                    mx0 = fmaxf(mx0, fmaxf(sf[j][0], sf[j][1]));
                    mx1 = fmaxf(mx1, fmaxf(sf[j][2], sf[j][3]));
                }
            }
            mx0 = fmaxf(mx0, __shfl_xor_sync(~0u, mx0, 1));
            mx0 = fmaxf(mx0, __shfl_xor_sync(~0u, mx0, 2));
            mx1 = fmaxf(mx1, __shfl_xor_sync(~0u, mx1, 1));
            mx1 = fmaxf(mx1, __shfl_xor_sync(~0u, mx1, 2));

            float mn0 = fmaxf(m0, mx0), mn1 = fmaxf(m1, mx1);
            float a0 = __expf(m0 - mn0), a1 = __expf(m1 - mn1);
            m0 = mn0; m1 = mn1;

            float rs0 = 0.f, rs1 = 0.f;
#pragma unroll
            for (int j = 0; j < 8; j++) {
                sf[j][0] = __expf(sf[j][0] - mn0); rs0 += sf[j][0];
                sf[j][1] = __expf(sf[j][1] - mn0); rs0 += sf[j][1];
                sf[j][2] = __expf(sf[j][2] - mn1); rs1 += sf[j][2];
                sf[j][3] = __expf(sf[j][3] - mn1); rs1 += sf[j][3];
            }
            rs0 += __shfl_xor_sync(~0u, rs0, 1);
            rs0 += __shfl_xor_sync(~0u, rs0, 2);
            rs1 += __shfl_xor_sync(~0u, rs1, 1);
            rs1 += __shfl_xor_sync(~0u, rs1, 2);
            l0 = l0 * a0 + rs0;
            l1 = l1 * a1 + rs1;

            // skip the 128-reg rescale when exact no-op for the whole warp
            if (!__all_sync(0xffffffffu, (a0 == 1.f) && (a1 == 1.f))) {
#pragma unroll
                for (int f = 0; f < 32; f++) {
                    of[f][0] *= a0; of[f][1] *= a0;
                    of[f][2] *= a1; of[f][3] *= a1;
                }
            }

            uint32_t pa[4][4];
#pragma unroll
            for (int sj = 0; sj < 4; sj++) {
                pa[sj][0] = f22u(sf[2 * sj][0],     sf[2 * sj][1]);
                pa[sj][1] = f22u(sf[2 * sj][2],     sf[2 * sj][3]);
                pa[sj][2] = f22u(sf[2 * sj + 1][0], sf[2 * sj + 1][1]);
                pa[sj][3] = f22u(sf[2 * sj + 1][2], sf[2 * sj + 1][3]);
            }

#pragma unroll
            for (int sj = 0; sj < 4; sj++) {
#pragma unroll
                for (int hg = 0; hg < 16; hg++) {
                    uint32_t v[4];
                    ldsm4t(v, vb + sj * (16 * APITCH * 2) + hg * 32);
                    mma16816(of[hg * 2],     pa[sj], v[0], v[1]);
                    mma16816(of[hg * 2 + 1], pa[sj], v[2], v[3]);
                }
            }
        }
        __syncthreads();
        buf ^= 1;
    }

    float i0 = 1.f / l0, i1 = 1.f / l1;
    __half* ENC = (__half*)g_ENCh;
    size_t base0 = ((size_t)(b * 2048) + row0) * 4096 + n * 256 + colq;
    size_t base1 = ((size_t)(b * 2048) + row1) * 4096 + n * 256 + colq;
#pragma unroll
    for (int f = 0; f < 32; f++) {
        *(uint32_t*)(ENC + base0 + f * 8) = f22u(of[f][0] * i0, of[f][1] * i0);
        *(uint32_t*)(ENC + base1 + f * 8) = f22u(of[f][2] * i1, of[f][3] * i1);
    }
}

// ---------------- launch ------------------------------------------------------
extern "C" void kernel_launch(void* const* d_in, const int* in_sizes, int n_in,
                              void* d_out, int out_size)
{
    const float* x      = (const float*)d_in[0];
    const int*   segpos = (const int*)  d_in[1];
    const float* qw     = (const float*)d_in[3];
    const float* kvw    = (const float*)d_in[4];
    const float* ow     = (const float*)d_in[5];
    float* out = (float*)d_out;

    void *Xh, *Wth, *OWth, *QKVh, *ENCh;
    cudaGetSymbolAddress(&Xh,   g_Xh);
    cudaGetSymbolAddress(&Wth,  g_Wth);
    cudaGetSymbolAddress(&OWth, g_OWth);
    cudaGetSymbolAddress(&QKVh, g_QKVh);
    cudaGetSymbolAddress(&ENCh, g_ENCh);

    // fused prep: conv_x + pack_wt + pack_owt (one launch, full overlap)
    prep_all<<<57344, 256>>>(x, qw, kvw, ow);

    cudaFuncSetAttribute(hgemm<__half>, cudaFuncAttributeMaxDynamicSharedMemorySize, HGEMM_SMEM);
    cudaFuncSetAttribute(hgemm<float>,  cudaFuncAttributeMaxDynamicSharedMemorySize, HGEMM_SMEM);
    cudaFuncSetAttribute(attn_kernel,   cudaFuncAttributeMaxDynamicSharedMemorySize, ATTN_SMEM);

    // qkv = x @ Wt^T -> fp16  (M=4096, N=8192, K=3584)
    hgemm<__half><<<dim3(8192 / 128, 4096 / 128), 256, HGEMM_SMEM>>>(
        (const __half*)Xh, (const __half*)Wth, (__half*)QKVh, 8192, 3584);

    // RoPE + q scaling in place (fp16)
    rope_kernel<<<dim3(4096, 24), 128>>>(segpos);

    // fp16 flash attention -> ENCh
    attn_kernel<<<dim3(16, 16, 2), 256, ATTN_SMEM>>>();

    // out = ENC @ OWt^T -> fp32  (M=4096, N=3584, K=4096)
    hgemm<float><<<dim3(3584 / 128, 4096 / 128), 256, HGEMM_SMEM>>>(
        (const __half*)ENCh, (const __half*)OWth, out, 3584, 4096);
}

// round 12
// speedup vs baseline: 1.0044x; 1.0044x over previous
#include <cuda_runtime.h>
#include <cuda_fp16.h>
#include <math.h>
#include <stdint.h>

// B=2, T=2048, D=3584, N=16, K=8, H=256, WINDOW=1024, SOFT_CAP=50, SCALAR=0.0625

// ---------------- scratch (allocation-free device globals) -------------------
__device__ unsigned short g_Xh  [4096u * 3584u];  // x fp16
__device__ unsigned short g_Wth [8192u * 3584u];  // qkv weight [j][d] K-major fp16
__device__ unsigned short g_OWth[3584u * 4096u];  // o_w^T [d][j] K-major fp16
__device__ unsigned short g_QKVh[4096u * 8192u];  // [B*T][ q | k | v ] fp16
__device__ unsigned short g_ENCh[4096u * 4096u];  // attention output fp16

// ---------------- helpers -----------------------------------------------------
__device__ __forceinline__ uint32_t smem_u32(const void* p) {
    uint32_t a;
    asm("{ .reg .u64 t; cvta.to.shared.u64 t, %1; cvt.u32.u64 %0, t; }" : "=r"(a) : "l"(p));
    return a;
}
__device__ __forceinline__ void ldsm4(uint32_t* d, uint32_t addr) {
    asm volatile("ldmatrix.sync.aligned.m8n8.x4.shared.b16 {%0,%1,%2,%3}, [%4];"
                 : "=r"(d[0]), "=r"(d[1]), "=r"(d[2]), "=r"(d[3]) : "r"(addr));
}
__device__ __forceinline__ void ldsm4t(uint32_t* d, uint32_t addr) {
    asm volatile("ldmatrix.sync.aligned.m8n8.x4.trans.shared.b16 {%0,%1,%2,%3}, [%4];"
                 : "=r"(d[0]), "=r"(d[1]), "=r"(d[2]), "=r"(d[3]) : "r"(addr));
}
__device__ __forceinline__ void mma16816(float* c, const uint32_t* a, uint32_t b0, uint32_t b1) {
    asm volatile("mma.sync.aligned.m16n8k16.row.col.f32.f16.f16.f32 "
                 "{%0,%1,%2,%3}, {%4,%5,%6,%7}, {%8,%9}, {%0,%1,%2,%3};"
                 : "+f"(c[0]), "+f"(c[1]), "+f"(c[2]), "+f"(c[3])
                 : "r"(a[0]), "r"(a[1]), "r"(a[2]), "r"(a[3]), "r"(b0), "r"(b1));
}
__device__ __forceinline__ uint32_t f22u(float a, float b) {
    __half2 h = __floats2half2_rn(a, b);
    return *(uint32_t*)&h;
}
__device__ __forceinline__ void cpa16(uint32_t dst, const void* src) {
    asm volatile("cp.async.cg.shared.global [%0], [%1], 16;" :: "r"(dst), "l"(src));
}

// ---------------- prep A: conv_x + pack_wt (one launch) -----------------------
//   [0, 14336)       conv_x   (float4 per thread)
//   [14336, 43008)   pack_wt  (32x32 tile transpose)
__global__ __launch_bounds__(256) void prep_main(const float* __restrict__ x,
                                                 const float* __restrict__ qw,
                                                 const float* __restrict__ kvw)
{
    __shared__ float t[32][33];
    const int blk = blockIdx.x;
    const int c  = threadIdx.x & 31;
    const int r0 = threadIdx.x >> 5;

    if (blk < 14336) {
        size_t i = ((size_t)blk * 256 + threadIdx.x) * 4;
        float4 v = *(const float4*)(x + i);
        uint2 u = make_uint2(f22u(v.x, v.y), f22u(v.z, v.w));
        *(uint2*)((__half*)g_Xh + i) = u;
    } else {
        int lin = blk - 14336;
        int hd  = lin / 896;
        int rem = lin - hd * 896;
        int h0  = (rem / 112) << 5;
        int d0  = (rem % 112) << 5;
        const float* src = (hd < 16) ? (qw + (size_t)hd * 3584 * 256)
                                     : (kvw + (size_t)(hd - 16) * 3584 * 256);
#pragma unroll
        for (int r = r0; r < 32; r += 8)
            t[r][c] = src[(size_t)(d0 + r) * 256 + h0 + c];
        __syncthreads();
#pragma unroll
        for (int r = r0; r < 32; r += 8)
            g_Wth[(size_t)(hd * 256 + h0 + r) * 3584 + d0 + c] =
                __half_as_ushort(__float2half(t[c][r]));
    }
}

// ---------------- prep B: pack_owt (side stream) ------------------------------
__global__ __launch_bounds__(256) void prep_owt(const float* __restrict__ ow)
{
    __shared__ float t[32][33];
    const int c  = threadIdx.x & 31;
    const int r0 = threadIdx.x >> 5;
    int j0 = (blockIdx.x % 128) << 5;
    int d0 = (blockIdx.x / 128) << 5;
#pragma unroll
    for (int r = r0; r < 32; r += 8)
        t[r][c] = ow[(size_t)(j0 + r) * 3584 + d0 + c];
    __syncthreads();
#pragma unroll
    for (int r = r0; r < 32; r += 8)
        g_OWth[(size_t)(d0 + r) * 4096 + j0 + c] =
            __half_as_ushort(__float2half(t[c][r]));
}

// ------ fp16 HMMA GEMM: R10 config (CTA 128x128, warp 32x64, 4-stage) ---------
// Params: ld = row stride of A and B (halves); klen = K extent to reduce;
// ACC: accumulate into C (fp32 path only).
#define PITCH 40
#define STAGE_B 20480
#define NSTG 4
#define HGEMM_SMEM (NSTG * STAGE_B)      // 81920 B -> 2 CTAs/SM

template <typename CT, bool ACC>
__global__ __launch_bounds__(256, 2) void hgemm(const __half* __restrict__ A,
                                                const __half* __restrict__ B,
                                                CT* __restrict__ C,
                                                int Nout, int ld, int klen)
{
    extern __shared__ __half hsm[];

    const int tid  = threadIdx.x;
    const int lane = tid & 31;
    const int wid  = tid >> 5;
    const int wm = (wid & 3) << 5;
    const int wn = (wid >> 2) << 6;
    const int m0 = blockIdx.y << 7;
    const int n0 = blockIdx.x << 7;
    const int nk = klen >> 5;

    const int lrow = tid >> 1;
    const int lcol = (tid & 1) << 4;
    const __half* ag = A + (size_t)(m0 + lrow) * ld + lcol;
    const __half* bg = B + (size_t)(n0 + lrow) * ld + lcol;

    uint32_t sb  = smem_u32(hsm);
    uint32_t sa  = sb + (uint32_t)(lrow * PITCH + lcol) * 2;
    uint32_t sbq = sa + 10240;

    const uint32_t lq = lane & 15;
    const uint32_t lh = (lane >> 4) << 4;
    uint32_t abase = sb + ((wm + lq) * PITCH) * 2 + lh;
    uint32_t bbase = sb + 10240 + ((wn + lq) * PITCH) * 2 + lh;

    float acc[2][8][4];
#pragma unroll
    for (int i = 0; i < 2; i++)
#pragma unroll
        for (int j = 0; j < 8; j++)
#pragma unroll
            for (int q = 0; q < 4; q++) acc[i][j][q] = 0.f;

#define HLOAD(i, s) do {                                                          \
    uint32_t _da = sa + (uint32_t)(s) * STAGE_B;                                  \
    uint32_t _db = sbq + (uint32_t)(s) * STAGE_B;                                 \
    const __half* _a = ag + ((i) << 5);                                           \
    const __half* _b = bg + ((i) << 5);                                           \
    asm volatile("cp.async.cg.shared.global [%0], [%1], 16;\n\t"                  \
                 "cp.async.cg.shared.global [%2], [%3], 16;\n\t"                  \
                 "cp.async.cg.shared.global [%4], [%5], 16;\n\t"                  \
                 "cp.async.cg.shared.global [%6], [%7], 16;\n\t"                  \
                 "cp.async.commit_group;"                                         \
                 :: "r"(_da), "l"(_a), "r"(_da + 16), "l"(_a + 8),                \
                    "r"(_db), "l"(_b), "r"(_db + 16), "l"(_b + 8));               \
} while (0)

    HLOAD(0, 0);
    HLOAD(1, 1);
    HLOAD(2, 2);

    for (int i = 0; i < nk; i++) {
        if (i < nk - 2)       asm volatile("cp.async.wait_group 2;");
        else if (i == nk - 2) asm volatile("cp.async.wait_group 1;");
        else                  asm volatile("cp.async.wait_group 0;");
        __syncthreads();
        if (i + 3 < nk) HLOAD(i + 3, (i + 3) & 3);

        uint32_t so = (uint32_t)(i & 3) * STAGE_B;
        uint32_t ab = abase + so;
        uint32_t bb = bbase + so;
#pragma unroll
        for (int ks = 0; ks < 2; ks++) {
            uint32_t af[2][4], bf[4][4];
            ldsm4(af[0], ab + ks * 32);
            ldsm4(af[1], ab + 16 * PITCH * 2 + ks * 32);
#pragma unroll
            for (int p = 0; p < 4; p++)
                ldsm4(bf[p], bb + p * (16 * PITCH * 2) + ks * 32);
#pragma unroll
            for (int mt = 0; mt < 2; mt++)
#pragma unroll
                for (int p = 0; p < 4; p++) {
                    mma16816(acc[mt][2 * p],     af[mt], bf[p][0], bf[p][2]);
                    mma16816(acc[mt][2 * p + 1], af[mt], bf[p][1], bf[p][3]);
                }
        }
    }

    const int g  = lane >> 2;
    const int cc = (lane & 3) << 1;
#pragma unroll
    for (int mt = 0; mt < 2; mt++) {
        int r = m0 + wm + mt * 16 + g;
#pragma unroll
        for (int nt = 0; nt < 8; nt++) {
            size_t off = (size_t)r * Nout + n0 + wn + nt * 8 + cc;
            if (sizeof(CT) == 2) {
                __half* cp = (__half*)C + off;
                *(uint32_t*)cp = f22u(acc[mt][nt][0], acc[mt][nt][1]);
                *(uint32_t*)(cp + (size_t)8 * Nout) = f22u(acc[mt][nt][2], acc[mt][nt][3]);
            } else {
                float* cp = (float*)C + off;
                if (ACC) {
                    float2 o0 = *(float2*)cp;
                    float2 o1 = *(float2*)(cp + (size_t)8 * Nout);
                    *(float2*)cp = make_float2(o0.x + acc[mt][nt][0], o0.y + acc[mt][nt][1]);
                    *(float2*)(cp + (size_t)8 * Nout) =
                        make_float2(o1.x + acc[mt][nt][2], o1.y + acc[mt][nt][3]);
                } else {
                    *(float2*)cp = make_float2(acc[mt][nt][0], acc[mt][nt][1]);
                    *(float2*)(cp + (size_t)8 * Nout) = make_float2(acc[mt][nt][2], acc[mt][nt][3]);
                }
            }
        }
    }
}

// ---------------- RoPE (+ q scaling), in place on fp16 QKV --------------------
__global__ __launch_bounds__(128) void rope_kernel(const int* __restrict__ segpos)
{
    int bt = blockIdx.x;
    int hh = blockIdx.y;
    int i  = threadIdx.x;
    __half* p = (__half*)g_QKVh + (size_t)bt * 8192 + hh * 256;
    float pos = (float)segpos[bt];
    float ts  = powf(10000.0f, (float)i * (1.0f / 128.0f));
    float ang = pos / ts;
    float s, c;
    sincosf(ang, &s, &c);
    float a  = __half2float(p[i]);
    float b2 = __half2float(p[i + 128]);
    float o1 = a * c - b2 * s;
    float o2 = b2 * c + a * s;
    if (hh < 16) { o1 *= 0.0625f; o2 *= 0.0625f; }
    p[i]       = __float2half(o1);
    p[i + 128] = __float2half(o2);
}

// ---------------- fp16 tensor-core flash attention (R10 body + head offset) ---
#define APITCH 264
#define KS_OFF (128 * APITCH)
#define KS_SZ  (64 * APITCH)
#define VS_OFF (KS_OFF + 2 * KS_SZ)
#define ATTN_SMEM ((KS_OFF + 4 * KS_SZ) * 2)   // 202752 bytes

__global__ __launch_bounds__(256, 1) void attn_kernel(int hoff)
{
    extern __shared__ __half ash[];
    const int tid  = threadIdx.x;
    const int lane = tid & 31;
    const int w    = tid >> 5;
    const int t0   = (15 - blockIdx.x) << 7;   // heavy tiles scheduled first
    const int n    = blockIdx.y + hoff;
    const int b    = blockIdx.z;
    const int kh   = n >> 1;
    uint32_t sb = smem_u32(ash);

    const __half* qkvh = (const __half*)g_QKVh + (size_t)b * 2048 * 8192;

    {
        const __half* qs = qkvh + (size_t)t0 * 8192 + n * 256;
#pragma unroll
        for (int it = 0; it < 16; it++) {
            int slot = it * 256 + tid;
            int r = slot >> 5, cs = (slot & 31) << 3;
            cpa16(sb + (r * APITCH + cs) * 2, qs + (size_t)r * 8192 + cs);
        }
    }

    int smin = t0 - 1023; if (smin < 0) smin = 0;
    const int c0 = smin >> 6, c1 = (t0 + 127) >> 6;

    const int ldr = tid >> 5, ldc = (tid & 31) << 3;

#define LOADKV(sg0, bf) do {                                                       \
    const __half* _ks = qkvh + (size_t)(sg0) * 8192 + 4096 + kh * 256;             \
    uint32_t _kb = sb + (KS_OFF + (bf) * KS_SZ) * 2;                               \
    uint32_t _vb = sb + (VS_OFF + (bf) * KS_SZ) * 2;                               \
    _Pragma("unroll")                                                              \
    for (int _it = 0; _it < 8; _it++) {                                            \
        int _r = _it * 8 + ldr;                                                    \
        cpa16(_kb + (_r * APITCH + ldc) * 2, _ks + (size_t)_r * 8192 + ldc);       \
        cpa16(_vb + (_r * APITCH + ldc) * 2, _ks + (size_t)_r * 8192 + 2048 + ldc);\
    }                                                                              \
    asm volatile("cp.async.commit_group;");                                        \
} while (0)

    LOADKV(c0 << 6, 0);

    float of[32][4];
#pragma unroll
    for (int f = 0; f < 32; f++)
#pragma unroll
        for (int q = 0; q < 4; q++) of[f][q] = 0.f;
    float m0 = -1e30f, m1 = -1e30f, l0 = 0.f, l1 = 0.f;

    const uint32_t lq  = lane & 15;
    const uint32_t lh16 = (lane >> 4) << 4;
    uint32_t qb  = sb + (((w << 4) + lq) * APITCH) * 2 + lh16;
    uint32_t kvl = (lq * APITCH) * 2 + lh16;

    const int row0 = t0 + (w << 4) + (lane >> 2);
    const int row1 = row0 + 8;
    const int colq = (lane & 3) << 1;
    const int wr0 = t0 + (w << 4), wr1 = wr0 + 15;

    int buf = 0;
    for (int c = c0; c <= c1; c++) {
        const int sg0 = c << 6;
        if (c < c1) {
            LOADKV((c + 1) << 6, buf ^ 1);
            asm volatile("cp.async.wait_group 1;");
        } else {
            asm volatile("cp.async.wait_group 0;");
        }
        __syncthreads();

        if (sg0 <= wr1 && sg0 + 63 >= wr0 - 1023) {
            uint32_t kb = sb + (KS_OFF + buf * KS_SZ) * 2 + kvl;
            uint32_t vb = sb + (VS_OFF + buf * KS_SZ) * 2 + kvl;

            float sf[8][4];
#pragma unroll
            for (int j = 0; j < 8; j++)
#pragma unroll
                for (int q = 0; q < 4; q++) sf[j][q] = 0.f;

#pragma unroll
            for (int kk = 0; kk < 16; kk++) {
                uint32_t a[4];
                ldsm4(a, qb + kk * 32);
#pragma unroll
                for (int ng = 0; ng < 4; ng++) {
                    uint32_t bfr[4];
                    ldsm4(bfr, kb + ng * (16 * APITCH * 2) + kk * 32);
                    mma16816(sf[ng * 2],     a, bfr[0], bfr[2]);
                    mma16816(sf[ng * 2 + 1], a, bfr[1], bfr[3]);
                }
            }

            float mx0 = -1e30f, mx1 = -1e30f;
#pragma unroll
            for (int j = 0; j < 8; j++) {
                int col = sg0 + j * 8 + colq;
#pragma unroll
                for (int q = 0; q < 4; q++) {
                    float e = __expf(sf[j][q] * 0.04f);
                    float s = 50.f * __fdividef(e - 1.f, e + 1.f);
                    int rr = (q < 2) ? row0 : row1;
                    int cc2 = col + (q & 1);
                    bool ok = (cc2 <= rr) && (cc2 >= rr - 1023);
                    sf[j][q] = ok ? s : -1e30f;
                }
                mx0 = fmaxf(mx0, fmaxf(sf[j][0], sf[j][1]));
                mx1 = fmaxf(mx1, fmaxf(sf[j][2], sf[j][3]));
            }
            mx0 = fmaxf(mx0, __shfl_xor_sync(~0u, mx0, 1));
            mx0 = fmaxf(mx0, __shfl_xor_sync(~0u, mx0, 2));
            mx1 = fmaxf(mx1, __shfl_xor_sync(~0u, mx1, 1));
            mx1 = fmaxf(mx1, __shfl_xor_sync(~0u, mx1, 2));

            float mn0 = fmaxf(m0, mx0), mn1 = fmaxf(m1, mx1);
            float a0 = __expf(m0 - mn0), a1 = __expf(m1 - mn1);
            m0 = mn0; m1 = mn1;

            float rs0 = 0.f, rs1 = 0.f;
#pragma unroll
            for (int j = 0; j < 8; j++) {
                sf[j][0] = __expf(sf[j][0] - mn0); rs0 += sf[j][0];
                sf[j][1] = __expf(sf[j][1] - mn0); rs0 += sf[j][1];
                sf[j][2] = __expf(sf[j][2] - mn1); rs1 += sf[j][2];
                sf[j][3] = __expf(sf[j][3] - mn1); rs1 += sf[j][3];
            }
            rs0 += __shfl_xor_sync(~0u, rs0, 1);
            rs0 += __shfl_xor_sync(~0u, rs0, 2);
            rs1 += __shfl_xor_sync(~0u, rs1, 1);
            rs1 += __shfl_xor_sync(~0u, rs1, 2);
            l0 = l0 * a0 + rs0;
            l1 = l1 * a1 + rs1;

#pragma unroll
            for (int f = 0; f < 32; f++) {
                of[f][0] *= a0; of[f][1] *= a0;
                of[f][2] *= a1; of[f][3] *= a1;
            }

            uint32_t pa[4][4];
#pragma unroll
            for (int sj = 0; sj < 4; sj++) {
                pa[sj][0] = f22u(sf[2 * sj][0],     sf[2 * sj][1]);
                pa[sj][1] = f22u(sf[2 * sj][2],     sf[2 * sj][3]);
                pa[sj][2] = f22u(sf[2 * sj + 1][0], sf[2 * sj + 1][1]);
                pa[sj][3] = f22u(sf[2 * sj + 1][2], sf[2 * sj + 1][3]);
            }

#pragma unroll
            for (int sj = 0; sj < 4; sj++) {
#pragma unroll
                for (int hg = 0; hg < 16; hg++) {
                    uint32_t v[4];
                    ldsm4t(v, vb + sj * (16 * APITCH * 2) + hg * 32);
                    mma16816(of[hg * 2],     pa[sj], v[0], v[1]);
                    mma16816(of[hg * 2 + 1], pa[sj], v[2], v[3]);
                }
            }
        }
        __syncthreads();
        buf ^= 1;
    }

    float i0 = 1.f / l0, i1 = 1.f / l1;
    __half* ENC = (__half*)g_ENCh;
    size_t base0 = ((size_t)(b * 2048) + row0) * 4096 + n * 256 + colq;
    size_t base1 = ((size_t)(b * 2048) + row1) * 4096 + n * 256 + colq;
#pragma unroll
    for (int f = 0; f < 32; f++) {
        *(uint32_t*)(ENC + base0 + f * 8) = f22u(of[f][0] * i0, of[f][1] * i0);
        *(uint32_t*)(ENC + base1 + f * 8) = f22u(of[f][2] * i1, of[f][3] * i1);
    }
}

// ---------------- launch: fork-join two-stream schedule -----------------------
extern "C" void kernel_launch(void* const* d_in, const int* in_sizes, int n_in,
                              void* d_out, int out_size)
{
    const float* x      = (const float*)d_in[0];
    const int*   segpos = (const int*)  d_in[1];
    const float* qw     = (const float*)d_in[3];
    const float* kvw    = (const float*)d_in[4];
    const float* ow     = (const float*)d_in[5];
    float* out = (float*)d_out;

    void *Xh, *Wth, *OWth, *QKVh, *ENCh;
    cudaGetSymbolAddress(&Xh,   g_Xh);
    cudaGetSymbolAddress(&Wth,  g_Wth);
    cudaGetSymbolAddress(&OWth, g_OWth);
    cudaGetSymbolAddress(&QKVh, g_QKVh);
    cudaGetSymbolAddress(&ENCh, g_ENCh);

    static cudaStream_t s2 = nullptr;
    static cudaEvent_t evRoot = nullptr, evH0 = nullptr, ev2a = nullptr;
    if (!s2) {
        cudaStreamCreateWithFlags(&s2, cudaStreamNonBlocking);
        cudaEventCreateWithFlags(&evRoot, cudaEventDisableTiming);
        cudaEventCreateWithFlags(&evH0,   cudaEventDisableTiming);
        cudaEventCreateWithFlags(&ev2a,   cudaEventDisableTiming);
    }

    cudaFuncSetAttribute((const void*)hgemm<__half, false>,
                         cudaFuncAttributeMaxDynamicSharedMemorySize, HGEMM_SMEM);
    cudaFuncSetAttribute((const void*)hgemm<float, false>,
                         cudaFuncAttributeMaxDynamicSharedMemorySize, HGEMM_SMEM);
    cudaFuncSetAttribute((const void*)hgemm<float, true>,
                         cudaFuncAttributeMaxDynamicSharedMemorySize, HGEMM_SMEM);
    cudaFuncSetAttribute((const void*)attn_kernel,
                         cudaFuncAttributeMaxDynamicSharedMemorySize, ATTN_SMEM);

    // fork: s2 handles pack_owt (+ later hgemm2a) in parallel with main chain
    cudaEventRecord(evRoot, 0);
    cudaStreamWaitEvent(s2, evRoot, 0);
    prep_owt<<<14336, 256, 0, s2>>>(ow);

    // main chain
    prep_main<<<43008, 256>>>(x, qw, kvw);
    hgemm<__half, false><<<dim3(64, 32), 256, HGEMM_SMEM>>>(
        (const __half*)Xh, (const __half*)Wth, (__half*)QKVh, 8192, 3584, 3584);
    rope_kernel<<<dim3(4096, 24), 128>>>(segpos);

    // attention heads 0-7 -> ENC cols [0, 2048)
    attn_kernel<<<dim3(16, 8, 2), 256, ATTN_SMEM>>>(0);
    cudaEventRecord(evH0, 0);

    // s2: out = ENC[:, :2048] @ OW[:2048] (beta=0), overlaps attn heads 8-15
    cudaStreamWaitEvent(s2, evH0, 0);
    hgemm<float, false><<<dim3(28, 32), 256, HGEMM_SMEM, s2>>>(
        (const __half*)ENCh, (const __half*)OWth, out, 3584, 4096, 2048);
    cudaEventRecord(ev2a, s2);

    // main: attention heads 8-15 -> ENC cols [2048, 4096)
    attn_kernel<<<dim3(16, 8, 2), 256, ATTN_SMEM>>>(8);

    // join: out += ENC[:, 2048:] @ OW[2048:]
    cudaStreamWaitEvent(0, ev2a, 0);
    hgemm<float, true><<<dim3(28, 32), 256, HGEMM_SMEM>>>(
        (const __half*)ENCh + 2048, (const __half*)OWth + 2048, out, 3584, 4096, 2048);
}

// round 13
// speedup vs baseline: 1.0401x; 1.0355x over previous
#include <cuda_runtime.h>
#include <cuda_fp16.h>
#include <math.h>
#include <stdint.h>

// B=2, T=2048, D=3584, N=16, K=8, H=256, WINDOW=1024, SOFT_CAP=50, SCALAR=0.0625

// ---------------- scratch (allocation-free device globals) -------------------
__device__ unsigned short g_Xh  [4096u * 3584u];  // x fp16
__device__ unsigned short g_Wth [8192u * 3584u];  // qkv weight [j][d] K-major fp16
__device__ unsigned short g_OWth[3584u * 4096u];  // o_w^T [d][j] K-major fp16
__device__ unsigned short g_QKVh[4096u * 8192u];  // [B*T][ q | k | v ] fp16
__device__ unsigned short g_ENCh[4096u * 4096u];  // attention output fp16
__device__ float          g_ts  [128];            // RoPE timescales (powf table)

// ---------------- helpers -----------------------------------------------------
__device__ __forceinline__ uint32_t smem_u32(const void* p) {
    uint32_t a;
    asm("{ .reg .u64 t; cvta.to.shared.u64 t, %1; cvt.u32.u64 %0, t; }" : "=r"(a) : "l"(p));
    return a;
}
__device__ __forceinline__ void ldsm4(uint32_t* d, uint32_t addr) {
    asm volatile("ldmatrix.sync.aligned.m8n8.x4.shared.b16 {%0,%1,%2,%3}, [%4];"
                 : "=r"(d[0]), "=r"(d[1]), "=r"(d[2]), "=r"(d[3]) : "r"(addr));
}
__device__ __forceinline__ void ldsm4t(uint32_t* d, uint32_t addr) {
    asm volatile("ldmatrix.sync.aligned.m8n8.x4.trans.shared.b16 {%0,%1,%2,%3}, [%4];"
                 : "=r"(d[0]), "=r"(d[1]), "=r"(d[2]), "=r"(d[3]) : "r"(addr));
}
__device__ __forceinline__ void mma16816(float* c, const uint32_t* a, uint32_t b0, uint32_t b1) {
    asm volatile("mma.sync.aligned.m16n8k16.row.col.f32.f16.f16.f32 "
                 "{%0,%1,%2,%3}, {%4,%5,%6,%7}, {%8,%9}, {%0,%1,%2,%3};"
                 : "+f"(c[0]), "+f"(c[1]), "+f"(c[2]), "+f"(c[3])
                 : "r"(a[0]), "r"(a[1]), "r"(a[2]), "r"(a[3]), "r"(b0), "r"(b1));
}
__device__ __forceinline__ uint32_t f22u(float a, float b) {
    __half2 h = __floats2half2_rn(a, b);
    return *(uint32_t*)&h;
}
__device__ __forceinline__ void cpa16(uint32_t dst, const void* src) {
    asm volatile("cp.async.cg.shared.global [%0], [%1], 16;" :: "r"(dst), "l"(src));
}

// ---------------- fused prep: conv_x + pack_wt + pack_owt + ts table ----------
//   [0, 14336)          conv_x   (float4 per thread)
//   [14336, 43008)      pack_wt  (32x32 tile transpose)
//   [43008, 57344)      pack_owt (32x32 tile transpose)
//   57344               RoPE timescale table (threads 0-127)
__global__ __launch_bounds__(256) void prep_all(const float* __restrict__ x,
                                                const float* __restrict__ qw,
                                                const float* __restrict__ kvw,
                                                const float* __restrict__ ow)
{
    __shared__ float t[32][33];
    const int blk = blockIdx.x;
    const int c  = threadIdx.x & 31;
    const int r0 = threadIdx.x >> 5;

    if (blk < 14336) {
        size_t i = ((size_t)blk * 256 + threadIdx.x) * 4;
        float4 v = *(const float4*)(x + i);
        uint2 u = make_uint2(f22u(v.x, v.y), f22u(v.z, v.w));
        *(uint2*)((__half*)g_Xh + i) = u;
    } else if (blk < 43008) {
        int lin = blk - 14336;
        int hd  = lin / 896;
        int rem = lin - hd * 896;
        int h0  = (rem / 112) << 5;
        int d0  = (rem % 112) << 5;
        const float* src = (hd < 16) ? (qw + (size_t)hd * 3584 * 256)
                                     : (kvw + (size_t)(hd - 16) * 3584 * 256);
#pragma unroll
        for (int r = r0; r < 32; r += 8)
            t[r][c] = src[(size_t)(d0 + r) * 256 + h0 + c];
        __syncthreads();
#pragma unroll
        for (int r = r0; r < 32; r += 8)
            g_Wth[(size_t)(hd * 256 + h0 + r) * 3584 + d0 + c] =
                __half_as_ushort(__float2half(t[c][r]));
    } else if (blk < 57344) {
        int lin = blk - 43008;
        int j0  = (lin % 128) << 5;
        int d0  = (lin / 128) << 5;
#pragma unroll
        for (int r = r0; r < 32; r += 8)
            t[r][c] = ow[(size_t)(j0 + r) * 3584 + d0 + c];
        __syncthreads();
#pragma unroll
        for (int r = r0; r < 32; r += 8)
            g_OWth[(size_t)(d0 + r) * 4096 + j0 + c] =
                __half_as_ushort(__float2half(t[c][r]));
    } else {
        // RoPE timescales: identical powf as before, computed ONCE
        int i = threadIdx.x;
        if (i < 128)
            g_ts[i] = powf(10000.0f, (float)i * (1.0f / 128.0f));
    }
}

// ------ fp16 HMMA GEMM: R10 config (CTA 128x128, warp 32x64, 4-stage) ---------
#define PITCH 40
#define STAGE_B 20480
#define NSTG 4
#define HGEMM_SMEM (NSTG * STAGE_B)      // 81920 B -> 2 CTAs/SM

template <typename CT>
__global__ __launch_bounds__(256, 2) void hgemm(const __half* __restrict__ A,
                                                const __half* __restrict__ B,
                                                CT* __restrict__ C,
                                                int Nout, int Kdim)
{
    extern __shared__ __half hsm[];

    const int tid  = threadIdx.x;
    const int lane = tid & 31;
    const int wid  = tid >> 5;
    const int wm = (wid & 3) << 5;
    const int wn = (wid >> 2) << 6;
    const int m0 = blockIdx.y << 7;
    const int n0 = blockIdx.x << 7;
    const int nk = Kdim >> 5;

    const int lrow = tid >> 1;
    const int lcol = (tid & 1) << 4;
    const __half* ag = A + (size_t)(m0 + lrow) * Kdim + lcol;
    const __half* bg = B + (size_t)(n0 + lrow) * Kdim + lcol;

    uint32_t sb  = smem_u32(hsm);
    uint32_t sa  = sb + (uint32_t)(lrow * PITCH + lcol) * 2;
    uint32_t sbq = sa + 10240;

    const uint32_t lq = lane & 15;
    const uint32_t lh = (lane >> 4) << 4;
    uint32_t abase = sb + ((wm + lq) * PITCH) * 2 + lh;
    uint32_t bbase = sb + 10240 + ((wn + lq) * PITCH) * 2 + lh;

    float acc[2][8][4];
#pragma unroll
    for (int i = 0; i < 2; i++)
#pragma unroll
        for (int j = 0; j < 8; j++)
#pragma unroll
            for (int q = 0; q < 4; q++) acc[i][j][q] = 0.f;

#define HLOAD(i, s) do {                                                          \
    uint32_t _da = sa + (uint32_t)(s) * STAGE_B;                                  \
    uint32_t _db = sbq + (uint32_t)(s) * STAGE_B;                                 \
    const __half* _a = ag + ((i) << 5);                                           \
    const __half* _b = bg + ((i) << 5);                                           \
    asm volatile("cp.async.cg.shared.global [%0], [%1], 16;\n\t"                  \
                 "cp.async.cg.shared.global [%2], [%3], 16;\n\t"                  \
                 "cp.async.cg.shared.global [%4], [%5], 16;\n\t"                  \
                 "cp.async.cg.shared.global [%6], [%7], 16;\n\t"                  \
                 "cp.async.commit_group;"                                         \
                 :: "r"(_da), "l"(_a), "r"(_da + 16), "l"(_a + 8),                \
                    "r"(_db), "l"(_b), "r"(_db + 16), "l"(_b + 8));               \
} while (0)

    HLOAD(0, 0);
    HLOAD(1, 1);
    HLOAD(2, 2);

    for (int i = 0; i < nk; i++) {
        if (i < nk - 2)       asm volatile("cp.async.wait_group 2;");
        else if (i == nk - 2) asm volatile("cp.async.wait_group 1;");
        else                  asm volatile("cp.async.wait_group 0;");
        __syncthreads();
        if (i + 3 < nk) HLOAD(i + 3, (i + 3) & 3);

        uint32_t so = (uint32_t)(i & 3) * STAGE_B;
        uint32_t ab = abase + so;
        uint32_t bb = bbase + so;
#pragma unroll
        for (int ks = 0; ks < 2; ks++) {
            uint32_t af[2][4], bf[4][4];
            ldsm4(af[0], ab + ks * 32);
            ldsm4(af[1], ab + 16 * PITCH * 2 + ks * 32);
#pragma unroll
            for (int p = 0; p < 4; p++)
                ldsm4(bf[p], bb + p * (16 * PITCH * 2) + ks * 32);
#pragma unroll
            for (int mt = 0; mt < 2; mt++)
#pragma unroll
                for (int p = 0; p < 4; p++) {
                    mma16816(acc[mt][2 * p],     af[mt], bf[p][0], bf[p][2]);
                    mma16816(acc[mt][2 * p + 1], af[mt], bf[p][1], bf[p][3]);
                }
        }
    }

    const int g  = lane >> 2;
    const int cc = (lane & 3) << 1;
#pragma unroll
    for (int mt = 0; mt < 2; mt++) {
        int r = m0 + wm + mt * 16 + g;
#pragma unroll
        for (int nt = 0; nt < 8; nt++) {
            size_t off = (size_t)r * Nout + n0 + wn + nt * 8 + cc;
            if (sizeof(CT) == 2) {
                __half* cp = (__half*)C + off;
                *(uint32_t*)cp = f22u(acc[mt][nt][0], acc[mt][nt][1]);
                *(uint32_t*)(cp + (size_t)8 * Nout) = f22u(acc[mt][nt][2], acc[mt][nt][3]);
            } else {
                float* cp = (float*)C + off;
                *(float2*)cp = make_float2(acc[mt][nt][0], acc[mt][nt][1]);
                *(float2*)(cp + (size_t)8 * Nout) = make_float2(acc[mt][nt][2], acc[mt][nt][3]);
            }
        }
    }
}

// ---------------- RoPE (+ q scaling), table-based timescale -------------------
__global__ __launch_bounds__(128) void rope_kernel(const int* __restrict__ segpos)
{
    int bt = blockIdx.x;
    int hh = blockIdx.y;
    int i  = threadIdx.x;
    __half* p = (__half*)g_QKVh + (size_t)bt * 8192 + hh * 256;
    float pos = (float)segpos[bt];
    float ts  = g_ts[i];                  // same powf value, computed once in prep
    float ang = pos / ts;                 // identical math path to reference
    float s, c;
    sincosf(ang, &s, &c);
    float a  = __half2float(p[i]);
    float b2 = __half2float(p[i + 128]);
    float o1 = a * c - b2 * s;
    float o2 = b2 * c + a * s;
    if (hh < 16) { o1 *= 0.0625f; o2 *= 0.0625f; }
    p[i]       = __float2half(o1);
    p[i + 128] = __float2half(o2);
}

// ---------------- fp16 tensor-core flash attention (R10, unchanged) -----------
#define APITCH 264
#define KS_OFF (128 * APITCH)
#define KS_SZ  (64 * APITCH)
#define VS_OFF (KS_OFF + 2 * KS_SZ)
#define ATTN_SMEM ((KS_OFF + 4 * KS_SZ) * 2)   // 202752 bytes

__global__ __launch_bounds__(256, 1) void attn_kernel()
{
    extern __shared__ __half ash[];
    const int tid  = threadIdx.x;
    const int lane = tid & 31;
    const int w    = tid >> 5;
    const int t0   = (15 - blockIdx.x) << 7;   // heavy tiles scheduled first
    const int n    = blockIdx.y;
    const int b    = blockIdx.z;
    const int kh   = n >> 1;
    uint32_t sb = smem_u32(ash);

    const __half* qkvh = (const __half*)g_QKVh + (size_t)b * 2048 * 8192;

    {
        const __half* qs = qkvh + (size_t)t0 * 8192 + n * 256;
#pragma unroll
        for (int it = 0; it < 16; it++) {
            int slot = it * 256 + tid;
            int r = slot >> 5, cs = (slot & 31) << 3;
            cpa16(sb + (r * APITCH + cs) * 2, qs + (size_t)r * 8192 + cs);
        }
    }

    int smin = t0 - 1023; if (smin < 0) smin = 0;
    const int c0 = smin >> 6, c1 = (t0 + 127) >> 6;

    const int ldr = tid >> 5, ldc = (tid & 31) << 3;

#define LOADKV(sg0, bf) do {                                                       \
    const __half* _ks = qkvh + (size_t)(sg0) * 8192 + 4096 + kh * 256;             \
    uint32_t _kb = sb + (KS_OFF + (bf) * KS_SZ) * 2;                               \
    uint32_t _vb = sb + (VS_OFF + (bf) * KS_SZ) * 2;                               \
    _Pragma("unroll")                                                              \
    for (int _it = 0; _it < 8; _it++) {                                            \
        int _r = _it * 8 + ldr;                                                    \
        cpa16(_kb + (_r * APITCH + ldc) * 2, _ks + (size_t)_r * 8192 + ldc);       \
        cpa16(_vb + (_r * APITCH + ldc) * 2, _ks + (size_t)_r * 8192 + 2048 + ldc);\
    }                                                                              \
    asm volatile("cp.async.commit_group;");                                        \
} while (0)

    LOADKV(c0 << 6, 0);

    float of[32][4];
#pragma unroll
    for (int f = 0; f < 32; f++)
#pragma unroll
        for (int q = 0; q < 4; q++) of[f][q] = 0.f;
    float m0 = -1e30f, m1 = -1e30f, l0 = 0.f, l1 = 0.f;

    const uint32_t lq  = lane & 15;
    const uint32_t lh16 = (lane >> 4) << 4;
    uint32_t qb  = sb + (((w << 4) + lq) * APITCH) * 2 + lh16;
    uint32_t kvl = (lq * APITCH) * 2 + lh16;

    const int row0 = t0 + (w << 4) + (lane >> 2);
    const int row1 = row0 + 8;
    const int colq = (lane & 3) << 1;
    const int wr0 = t0 + (w << 4), wr1 = wr0 + 15;

    int buf = 0;
    for (int c = c0; c <= c1; c++) {
        const int sg0 = c << 6;
        if (c < c1) {
            LOADKV((c + 1) << 6, buf ^ 1);
            asm volatile("cp.async.wait_group 1;");
        } else {
            asm volatile("cp.async.wait_group 0;");
        }
        __syncthreads();

        if (sg0 <= wr1 && sg0 + 63 >= wr0 - 1023) {
            uint32_t kb = sb + (KS_OFF + buf * KS_SZ) * 2 + kvl;
            uint32_t vb = sb + (VS_OFF + buf * KS_SZ) * 2 + kvl;

            float sf[8][4];
#pragma unroll
            for (int j = 0; j < 8; j++)
#pragma unroll
                for (int q = 0; q < 4; q++) sf[j][q] = 0.f;

#pragma unroll
            for (int kk = 0; kk < 16; kk++) {
                uint32_t a[4];
                ldsm4(a, qb + kk * 32);
#pragma unroll
                for (int ng = 0; ng < 4; ng++) {
                    uint32_t bfr[4];
                    ldsm4(bfr, kb + ng * (16 * APITCH * 2) + kk * 32);
                    mma16816(sf[ng * 2],     a, bfr[0], bfr[2]);
                    mma16816(sf[ng * 2 + 1], a, bfr[1], bfr[3]);
                }
            }

            float mx0 = -1e30f, mx1 = -1e30f;
#pragma unroll
            for (int j = 0; j < 8; j++) {
                int col = sg0 + j * 8 + colq;
#pragma unroll
                for (int q = 0; q < 4; q++) {
                    float e = __expf(sf[j][q] * 0.04f);
                    float s = 50.f * __fdividef(e - 1.f, e + 1.f);
                    int rr = (q < 2) ? row0 : row1;
                    int cc2 = col + (q & 1);
                    bool ok = (cc2 <= rr) && (cc2 >= rr - 1023);
                    sf[j][q] = ok ? s : -1e30f;
                }
                mx0 = fmaxf(mx0, fmaxf(sf[j][0], sf[j][1]));
                mx1 = fmaxf(mx1, fmaxf(sf[j][2], sf[j][3]));
            }
            mx0 = fmaxf(mx0, __shfl_xor_sync(~0u, mx0, 1));
            mx0 = fmaxf(mx0, __shfl_xor_sync(~0u, mx0, 2));
            mx1 = fmaxf(mx1, __shfl_xor_sync(~0u, mx1, 1));
            mx1 = fmaxf(mx1, __shfl_xor_sync(~0u, mx1, 2));

            float mn0 = fmaxf(m0, mx0), mn1 = fmaxf(m1, mx1);
            float a0 = __expf(m0 - mn0), a1 = __expf(m1 - mn1);
            m0 = mn0; m1 = mn1;

            float rs0 = 0.f, rs1 = 0.f;
#pragma unroll
            for (int j = 0; j < 8; j++) {
                sf[j][0] = __expf(sf[j][0] - mn0); rs0 += sf[j][0];
                sf[j][1] = __expf(sf[j][1] - mn0); rs0 += sf[j][1];
                sf[j][2] = __expf(sf[j][2] - mn1); rs1 += sf[j][2];
                sf[j][3] = __expf(sf[j][3] - mn1); rs1 += sf[j][3];
            }
            rs0 += __shfl_xor_sync(~0u, rs0, 1);
            rs0 += __shfl_xor_sync(~0u, rs0, 2);
            rs1 += __shfl_xor_sync(~0u, rs1, 1);
            rs1 += __shfl_xor_sync(~0u, rs1, 2);
            l0 = l0 * a0 + rs0;
            l1 = l1 * a1 + rs1;

#pragma unroll
            for (int f = 0; f < 32; f++) {
                of[f][0] *= a0; of[f][1] *= a0;
                of[f][2] *= a1; of[f][3] *= a1;
            }

            uint32_t pa[4][4];
#pragma unroll
            for (int sj = 0; sj < 4; sj++) {
                pa[sj][0] = f22u(sf[2 * sj][0],     sf[2 * sj][1]);
                pa[sj][1] = f22u(sf[2 * sj][2],     sf[2 * sj][3]);
                pa[sj][2] = f22u(sf[2 * sj + 1][0], sf[2 * sj + 1][1]);
                pa[sj][3] = f22u(sf[2 * sj + 1][2], sf[2 * sj + 1][3]);
            }

#pragma unroll
            for (int sj = 0; sj < 4; sj++) {
#pragma unroll
                for (int hg = 0; hg < 16; hg++) {
                    uint32_t v[4];
                    ldsm4t(v, vb + sj * (16 * APITCH * 2) + hg * 32);
                    mma16816(of[hg * 2],     pa[sj], v[0], v[1]);
                    mma16816(of[hg * 2 + 1], pa[sj], v[2], v[3]);
                }
            }
        }
        __syncthreads();
        buf ^= 1;
    }

    float i0 = 1.f / l0, i1 = 1.f / l1;
    __half* ENC = (__half*)g_ENCh;
    size_t base0 = ((size_t)(b * 2048) + row0) * 4096 + n * 256 + colq;
    size_t base1 = ((size_t)(b * 2048) + row1) * 4096 + n * 256 + colq;
#pragma unroll
    for (int f = 0; f < 32; f++) {
        *(uint32_t*)(ENC + base0 + f * 8) = f22u(of[f][0] * i0, of[f][1] * i0);
        *(uint32_t*)(ENC + base1 + f * 8) = f22u(of[f][2] * i1, of[f][3] * i1);
    }
}

// ---------------- launch (R10 single-stream schedule) --------------------------
extern "C" void kernel_launch(void* const* d_in, const int* in_sizes, int n_in,
                              void* d_out, int out_size)
{
    const float* x      = (const float*)d_in[0];
    const int*   segpos = (const int*)  d_in[1];
    const float* qw     = (const float*)d_in[3];
    const float* kvw    = (const float*)d_in[4];
    const float* ow     = (const float*)d_in[5];
    float* out = (float*)d_out;

    void *Xh, *Wth, *OWth, *QKVh, *ENCh;
    cudaGetSymbolAddress(&Xh,   g_Xh);
    cudaGetSymbolAddress(&Wth,  g_Wth);
    cudaGetSymbolAddress(&OWth, g_OWth);
    cudaGetSymbolAddress(&QKVh, g_QKVh);
    cudaGetSymbolAddress(&ENCh, g_ENCh);

    // fused prep: conv_x + pack_wt + pack_owt + ts table (one launch)
    prep_all<<<57345, 256>>>(x, qw, kvw, ow);

    cudaFuncSetAttribute(hgemm<__half>, cudaFuncAttributeMaxDynamicSharedMemorySize, HGEMM_SMEM);
    cudaFuncSetAttribute(hgemm<float>,  cudaFuncAttributeMaxDynamicSharedMemorySize, HGEMM_SMEM);
    cudaFuncSetAttribute(attn_kernel,   cudaFuncAttributeMaxDynamicSharedMemorySize, ATTN_SMEM);

    // qkv = x @ Wt^T -> fp16  (M=4096, N=8192, K=3584)
    hgemm<__half><<<dim3(8192 / 128, 4096 / 128), 256, HGEMM_SMEM>>>(
        (const __half*)Xh, (const __half*)Wth, (__half*)QKVh, 8192, 3584);

    // RoPE + q scaling in place (fp16, table-based timescales)
    rope_kernel<<<dim3(4096, 24), 128>>>(segpos);

    // fp16 flash attention -> ENCh (heavy-first tile order)
    attn_kernel<<<dim3(16, 16, 2), 256, ATTN_SMEM>>>();

    // out = ENC @ OWt^T -> fp32  (M=4096, N=3584, K=4096)
    hgemm<float><<<dim3(3584 / 128, 4096 / 128), 256, HGEMM_SMEM>>>(
        (const __half*)ENCh, (const __half*)OWth, out, 3584, 4096);
}

// round 14
// speedup vs baseline: 1.0406x; 1.0005x over previous
#include <cuda_runtime.h>
#include <cuda_fp16.h>
#include <math.h>
#include <stdint.h>

// B=2, T=2048, D=3584, N=16, K=8, H=256, WINDOW=1024, SOFT_CAP=50, SCALAR=0.0625

// ---------------- scratch (allocation-free device globals) -------------------
__device__ unsigned short g_Xh  [4096u * 3584u];  // x fp16
__device__ unsigned short g_Wth [8192u * 3584u];  // qkv weight [j][d] K-major fp16
__device__ unsigned short g_OWth[3584u * 4096u];  // o_w^T [d][j] K-major fp16
__device__ unsigned short g_QKVh[4096u * 8192u];  // [B*T][ q | k | v ] fp16
__device__ unsigned short g_ENCh[4096u * 4096u];  // attention output fp16
__device__ float          g_ts  [128];            // RoPE timescales (powf table)

// ---------------- helpers -----------------------------------------------------
__device__ __forceinline__ uint32_t smem_u32(const void* p) {
    uint32_t a;
    asm("{ .reg .u64 t; cvta.to.shared.u64 t, %1; cvt.u32.u64 %0, t; }" : "=r"(a) : "l"(p));
    return a;
}
__device__ __forceinline__ void ldsm4(uint32_t* d, uint32_t addr) {
    asm volatile("ldmatrix.sync.aligned.m8n8.x4.shared.b16 {%0,%1,%2,%3}, [%4];"
                 : "=r"(d[0]), "=r"(d[1]), "=r"(d[2]), "=r"(d[3]) : "r"(addr));
}
__device__ __forceinline__ void ldsm4t(uint32_t* d, uint32_t addr) {
    asm volatile("ldmatrix.sync.aligned.m8n8.x4.trans.shared.b16 {%0,%1,%2,%3}, [%4];"
                 : "=r"(d[0]), "=r"(d[1]), "=r"(d[2]), "=r"(d[3]) : "r"(addr));
}
__device__ __forceinline__ void mma16816(float* c, const uint32_t* a, uint32_t b0, uint32_t b1) {
    asm volatile("mma.sync.aligned.m16n8k16.row.col.f32.f16.f16.f32 "
                 "{%0,%1,%2,%3}, {%4,%5,%6,%7}, {%8,%9}, {%0,%1,%2,%3};"
                 : "+f"(c[0]), "+f"(c[1]), "+f"(c[2]), "+f"(c[3])
                 : "r"(a[0]), "r"(a[1]), "r"(a[2]), "r"(a[3]), "r"(b0), "r"(b1));
}
__device__ __forceinline__ uint32_t f22u(float a, float b) {
    __half2 h = __floats2half2_rn(a, b);
    return *(uint32_t*)&h;
}
__device__ __forceinline__ void cpa16(uint32_t dst, const void* src) {
    asm volatile("cp.async.cg.shared.global [%0], [%1], 16;" :: "r"(dst), "l"(src));
}

// ---------------- fused prep: conv_x + pack_wt + pack_owt + ts table ----------
__global__ __launch_bounds__(256) void prep_all(const float* __restrict__ x,
                                                const float* __restrict__ qw,
                                                const float* __restrict__ kvw,
                                                const float* __restrict__ ow)
{
    __shared__ float t[32][33];
    const int blk = blockIdx.x;
    const int c  = threadIdx.x & 31;
    const int r0 = threadIdx.x >> 5;

    if (blk < 14336) {
        size_t i = ((size_t)blk * 256 + threadIdx.x) * 4;
        float4 v = *(const float4*)(x + i);
        uint2 u = make_uint2(f22u(v.x, v.y), f22u(v.z, v.w));
        *(uint2*)((__half*)g_Xh + i) = u;
    } else if (blk < 43008) {
        int lin = blk - 14336;
        int hd  = lin / 896;
        int rem = lin - hd * 896;
        int h0  = (rem / 112) << 5;
        int d0  = (rem % 112) << 5;
        const float* src = (hd < 16) ? (qw + (size_t)hd * 3584 * 256)
                                     : (kvw + (size_t)(hd - 16) * 3584 * 256);
#pragma unroll
        for (int r = r0; r < 32; r += 8)
            t[r][c] = src[(size_t)(d0 + r) * 256 + h0 + c];
        __syncthreads();
#pragma unroll
        for (int r = r0; r < 32; r += 8)
            g_Wth[(size_t)(hd * 256 + h0 + r) * 3584 + d0 + c] =
                __half_as_ushort(__float2half(t[c][r]));
    } else if (blk < 57344) {
        int lin = blk - 43008;
        int j0  = (lin % 128) << 5;
        int d0  = (lin / 128) << 5;
#pragma unroll
        for (int r = r0; r < 32; r += 8)
            t[r][c] = ow[(size_t)(j0 + r) * 3584 + d0 + c];
        __syncthreads();
#pragma unroll
        for (int r = r0; r < 32; r += 8)
            g_OWth[(size_t)(d0 + r) * 4096 + j0 + c] =
                __half_as_ushort(__float2half(t[c][r]));
    } else {
        int i = threadIdx.x;
        if (i < 128)
            g_ts[i] = powf(10000.0f, (float)i * (1.0f / 128.0f));
    }
}

// ------ fp16 HMMA GEMM: R10 config + 8xM supertile rasterization --------------
#define PITCH 40
#define STAGE_B 20480
#define NSTG 4
#define HGEMM_SMEM (NSTG * STAGE_B)      // 81920 B -> 2 CTAs/SM

template <typename CT>
__global__ __launch_bounds__(256, 2) void hgemm(const __half* __restrict__ A,
                                                const __half* __restrict__ B,
                                                CT* __restrict__ C,
                                                int Nout, int Kdim)
{
    extern __shared__ __half hsm[];

    const int tid  = threadIdx.x;
    const int lane = tid & 31;
    const int wid  = tid >> 5;
    const int wm = (wid & 3) << 5;
    const int wn = (wid >> 2) << 6;

    // 8xM supertile swizzle: a wave covers 8 M-tiles x ~37 N-tiles, keeping
    // both operands' L2 working set ~41 MB (vs ~63 MB with linear order).
    // gridDim.y (=32) is divisible by 8 for both GEMMs -> exact mapping.
    const int lin = blockIdx.y * gridDim.x + blockIdx.x;
    const int tpg = gridDim.x << 3;          // tiles per supertile group
    const int grp = lin / tpg;
    const int rem = lin - grp * tpg;
    const int m0 = ((grp << 3) + (rem & 7)) << 7;
    const int n0 = (rem >> 3) << 7;

    const int nk = Kdim >> 5;

    const int lrow = tid >> 1;
    const int lcol = (tid & 1) << 4;
    const __half* ag = A + (size_t)(m0 + lrow) * Kdim + lcol;
    const __half* bg = B + (size_t)(n0 + lrow) * Kdim + lcol;

    uint32_t sb  = smem_u32(hsm);
    uint32_t sa  = sb + (uint32_t)(lrow * PITCH + lcol) * 2;
    uint32_t sbq = sa + 10240;

    const uint32_t lq = lane & 15;
    const uint32_t lh = (lane >> 4) << 4;
    uint32_t abase = sb + ((wm + lq) * PITCH) * 2 + lh;
    uint32_t bbase = sb + 10240 + ((wn + lq) * PITCH) * 2 + lh;

    float acc[2][8][4];
#pragma unroll
    for (int i = 0; i < 2; i++)
#pragma unroll
        for (int j = 0; j < 8; j++)
#pragma unroll
            for (int q = 0; q < 4; q++) acc[i][j][q] = 0.f;

#define HLOAD(i, s) do {                                                          \
    uint32_t _da = sa + (uint32_t)(s) * STAGE_B;                                  \
    uint32_t _db = sbq + (uint32_t)(s) * STAGE_B;                                 \
    const __half* _a = ag + ((i) << 5);                                           \
    const __half* _b = bg + ((i) << 5);                                           \
    asm volatile("cp.async.cg.shared.global [%0], [%1], 16;\n\t"                  \
                 "cp.async.cg.shared.global [%2], [%3], 16;\n\t"                  \
                 "cp.async.cg.shared.global [%4], [%5], 16;\n\t"                  \
                 "cp.async.cg.shared.global [%6], [%7], 16;\n\t"                  \
                 "cp.async.commit_group;"                                         \
                 :: "r"(_da), "l"(_a), "r"(_da + 16), "l"(_a + 8),                \
                    "r"(_db), "l"(_b), "r"(_db + 16), "l"(_b + 8));               \
} while (0)

    HLOAD(0, 0);
    HLOAD(1, 1);
    HLOAD(2, 2);

    for (int i = 0; i < nk; i++) {
        if (i < nk - 2)       asm volatile("cp.async.wait_group 2;");
        else if (i == nk - 2) asm volatile("cp.async.wait_group 1;");
        else                  asm volatile("cp.async.wait_group 0;");
        __syncthreads();
        if (i + 3 < nk) HLOAD(i + 3, (i + 3) & 3);

        uint32_t so = (uint32_t)(i & 3) * STAGE_B;
        uint32_t ab = abase + so;
        uint32_t bb = bbase + so;
#pragma unroll
        for (int ks = 0; ks < 2; ks++) {
            uint32_t af[2][4], bf[4][4];
            ldsm4(af[0], ab + ks * 32);
            ldsm4(af[1], ab + 16 * PITCH * 2 + ks * 32);
#pragma unroll
            for (int p = 0; p < 4; p++)
                ldsm4(bf[p], bb + p * (16 * PITCH * 2) + ks * 32);
#pragma unroll
            for (int mt = 0; mt < 2; mt++)
#pragma unroll
                for (int p = 0; p < 4; p++) {
                    mma16816(acc[mt][2 * p],     af[mt], bf[p][0], bf[p][2]);
                    mma16816(acc[mt][2 * p + 1], af[mt], bf[p][1], bf[p][3]);
                }
        }
    }

    const int g  = lane >> 2;
    const int cc = (lane & 3) << 1;
#pragma unroll
    for (int mt = 0; mt < 2; mt++) {
        int r = m0 + wm + mt * 16 + g;
#pragma unroll
        for (int nt = 0; nt < 8; nt++) {
            size_t off = (size_t)r * Nout + n0 + wn + nt * 8 + cc;
            if (sizeof(CT) == 2) {
                __half* cp = (__half*)C + off;
                *(uint32_t*)cp = f22u(acc[mt][nt][0], acc[mt][nt][1]);
                *(uint32_t*)(cp + (size_t)8 * Nout) = f22u(acc[mt][nt][2], acc[mt][nt][3]);
            } else {
                float* cp = (float*)C + off;
                *(float2*)cp = make_float2(acc[mt][nt][0], acc[mt][nt][1]);
                *(float2*)(cp + (size_t)8 * Nout) = make_float2(acc[mt][nt][2], acc[mt][nt][3]);
            }
        }
    }
}

// ---------------- RoPE (+ q scaling), table-based timescale -------------------
__global__ __launch_bounds__(128) void rope_kernel(const int* __restrict__ segpos)
{
    int bt = blockIdx.x;
    int hh = blockIdx.y;
    int i  = threadIdx.x;
    __half* p = (__half*)g_QKVh + (size_t)bt * 8192 + hh * 256;
    float pos = (float)segpos[bt];
    float ts  = g_ts[i];
    float ang = pos / ts;
    float s, c;
    sincosf(ang, &s, &c);
    float a  = __half2float(p[i]);
    float b2 = __half2float(p[i + 128]);
    float o1 = a * c - b2 * s;
    float o2 = b2 * c + a * s;
    if (hh < 16) { o1 *= 0.0625f; o2 *= 0.0625f; }
    p[i]       = __float2half(o1);
    p[i + 128] = __float2half(o2);
}

// ---------------- fp16 tensor-core flash attention (R10, unchanged) -----------
#define APITCH 264
#define KS_OFF (128 * APITCH)
#define KS_SZ  (64 * APITCH)
#define VS_OFF (KS_OFF + 2 * KS_SZ)
#define ATTN_SMEM ((KS_OFF + 4 * KS_SZ) * 2)   // 202752 bytes

__global__ __launch_bounds__(256, 1) void attn_kernel()
{
    extern __shared__ __half ash[];
    const int tid  = threadIdx.x;
    const int lane = tid & 31;
    const int w    = tid >> 5;
    const int t0   = (15 - blockIdx.x) << 7;   // heavy tiles scheduled first
    const int n    = blockIdx.y;
    const int b    = blockIdx.z;
    const int kh   = n >> 1;
    uint32_t sb = smem_u32(ash);

    const __half* qkvh = (const __half*)g_QKVh + (size_t)b * 2048 * 8192;

    {
        const __half* qs = qkvh + (size_t)t0 * 8192 + n * 256;
#pragma unroll
        for (int it = 0; it < 16; it++) {
            int slot = it * 256 + tid;
            int r = slot >> 5, cs = (slot & 31) << 3;
            cpa16(sb + (r * APITCH + cs) * 2, qs + (size_t)r * 8192 + cs);
        }
    }

    int smin = t0 - 1023; if (smin < 0) smin = 0;
    const int c0 = smin >> 6, c1 = (t0 + 127) >> 6;

    const int ldr = tid >> 5, ldc = (tid & 31) << 3;

#define LOADKV(sg0, bf) do {                                                       \
    const __half* _ks = qkvh + (size_t)(sg0) * 8192 + 4096 + kh * 256;             \
    uint32_t _kb = sb + (KS_OFF + (bf) * KS_SZ) * 2;                               \
    uint32_t _vb = sb + (VS_OFF + (bf) * KS_SZ) * 2;                               \
    _Pragma("unroll")                                                              \
    for (int _it = 0; _it < 8; _it++) {                                            \
        int _r = _it * 8 + ldr;                                                    \
        cpa16(_kb + (_r * APITCH + ldc) * 2, _ks + (size_t)_r * 8192 + ldc);       \
        cpa16(_vb + (_r * APITCH + ldc) * 2, _ks + (size_t)_r * 8192 + 2048 + ldc);\
    }                                                                              \
    asm volatile("cp.async.commit_group;");                                        \
} while (0)

    LOADKV(c0 << 6, 0);

    float of[32][4];
#pragma unroll
    for (int f = 0; f < 32; f++)
#pragma unroll
        for (int q = 0; q < 4; q++) of[f][q] = 0.f;
    float m0 = -1e30f, m1 = -1e30f, l0 = 0.f, l1 = 0.f;

    const uint32_t lq  = lane & 15;
    const uint32_t lh16 = (lane >> 4) << 4;
    uint32_t qb  = sb + (((w << 4) + lq) * APITCH) * 2 + lh16;
    uint32_t kvl = (lq * APITCH) * 2 + lh16;

    const int row0 = t0 + (w << 4) + (lane >> 2);
    const int row1 = row0 + 8;
    const int colq = (lane & 3) << 1;
    const int wr0 = t0 + (w << 4), wr1 = wr0 + 15;

    int buf = 0;
    for (int c = c0; c <= c1; c++) {
        const int sg0 = c << 6;
        if (c < c1) {
            LOADKV((c + 1) << 6, buf ^ 1);
            asm volatile("cp.async.wait_group 1;");
        } else {
            asm volatile("cp.async.wait_group 0;");
        }
        __syncthreads();

        if (sg0 <= wr1 && sg0 + 63 >= wr0 - 1023) {
            uint32_t kb = sb + (KS_OFF + buf * KS_SZ) * 2 + kvl;
            uint32_t vb = sb + (VS_OFF + buf * KS_SZ) * 2 + kvl;

            float sf[8][4];
#pragma unroll
            for (int j = 0; j < 8; j++)
#pragma unroll
                for (int q = 0; q < 4; q++) sf[j][q] = 0.f;

#pragma unroll
            for (int kk = 0; kk < 16; kk++) {
                uint32_t a[4];
                ldsm4(a, qb + kk * 32);
#pragma unroll
                for (int ng = 0; ng < 4; ng++) {
                    uint32_t bfr[4];
                    ldsm4(bfr, kb + ng * (16 * APITCH * 2) + kk * 32);
                    mma16816(sf[ng * 2],     a, bfr[0], bfr[2]);
                    mma16816(sf[ng * 2 + 1], a, bfr[1], bfr[3]);
                }
            }

            float mx0 = -1e30f, mx1 = -1e30f;
#pragma unroll
            for (int j = 0; j < 8; j++) {
                int col = sg0 + j * 8 + colq;
#pragma unroll
                for (int q = 0; q < 4; q++) {
                    float e = __expf(sf[j][q] * 0.04f);
                    float s = 50.f * __fdividef(e - 1.f, e + 1.f);
                    int rr = (q < 2) ? row0 : row1;
                    int cc2 = col + (q & 1);
                    bool ok = (cc2 <= rr) && (cc2 >= rr - 1023);
                    sf[j][q] = ok ? s : -1e30f;
                }
                mx0 = fmaxf(mx0, fmaxf(sf[j][0], sf[j][1]));
                mx1 = fmaxf(mx1, fmaxf(sf[j][2], sf[j][3]));
            }
            mx0 = fmaxf(mx0, __shfl_xor_sync(~0u, mx0, 1));
            mx0 = fmaxf(mx0, __shfl_xor_sync(~0u, mx0, 2));
            mx1 = fmaxf(mx1, __shfl_xor_sync(~0u, mx1, 1));
            mx1 = fmaxf(mx1, __shfl_xor_sync(~0u, mx1, 2));

            float mn0 = fmaxf(m0, mx0), mn1 = fmaxf(m1, mx1);
            float a0 = __expf(m0 - mn0), a1 = __expf(m1 - mn1);
            m0 = mn0; m1 = mn1;

            float rs0 = 0.f, rs1 = 0.f;
#pragma unroll
            for (int j = 0; j < 8; j++) {
                sf[j][0] = __expf(sf[j][0] - mn0); rs0 += sf[j][0];
                sf[j][1] = __expf(sf[j][1] - mn0); rs0 += sf[j][1];
                sf[j][2] = __expf(sf[j][2] - mn1); rs1 += sf[j][2];
                sf[j][3] = __expf(sf[j][3] - mn1); rs1 += sf[j][3];
            }
            rs0 += __shfl_xor_sync(~0u, rs0, 1);
            rs0 += __shfl_xor_sync(~0u, rs0, 2);
            rs1 += __shfl_xor_sync(~0u, rs1, 1);
            rs1 += __shfl_xor_sync(~0u, rs1, 2);
            l0 = l0 * a0 + rs0;
            l1 = l1 * a1 + rs1;

#pragma unroll
            for (int f = 0; f < 32; f++) {
                of[f][0] *= a0; of[f][1] *= a0;
                of[f][2] *= a1; of[f][3] *= a1;
            }

            uint32_t pa[4][4];
#pragma unroll
            for (int sj = 0; sj < 4; sj++) {
                pa[sj][0] = f22u(sf[2 * sj][0],     sf[2 * sj][1]);
                pa[sj][1] = f22u(sf[2 * sj][2],     sf[2 * sj][3]);
                pa[sj][2] = f22u(sf[2 * sj + 1][0], sf[2 * sj + 1][1]);
                pa[sj][3] = f22u(sf[2 * sj + 1][2], sf[2 * sj + 1][3]);
            }

#pragma unroll
            for (int sj = 0; sj < 4; sj++) {
#pragma unroll
                for (int hg = 0; hg < 16; hg++) {
                    uint32_t v[4];
                    ldsm4t(v, vb + sj * (16 * APITCH * 2) + hg * 32);
                    mma16816(of[hg * 2],     pa[sj], v[0], v[1]);
                    mma16816(of[hg * 2 + 1], pa[sj], v[2], v[3]);
                }
            }
        }
        __syncthreads();
        buf ^= 1;
    }

    float i0 = 1.f / l0, i1 = 1.f / l1;
    __half* ENC = (__half*)g_ENCh;
    size_t base0 = ((size_t)(b * 2048) + row0) * 4096 + n * 256 + colq;
    size_t base1 = ((size_t)(b * 2048) + row1) * 4096 + n * 256 + colq;
#pragma unroll
    for (int f = 0; f < 32; f++) {
        *(uint32_t*)(ENC + base0 + f * 8) = f22u(of[f][0] * i0, of[f][1] * i0);
        *(uint32_t*)(ENC + base1 + f * 8) = f22u(of[f][2] * i1, of[f][3] * i1);
    }
}

// ---------------- launch (single-stream schedule) -------------------------------
extern "C" void kernel_launch(void* const* d_in, const int* in_sizes, int n_in,
                              void* d_out, int out_size)
{
    const float* x      = (const float*)d_in[0];
    const int*   segpos = (const int*)  d_in[1];
    const float* qw     = (const float*)d_in[3];
    const float* kvw    = (const float*)d_in[4];
    const float* ow     = (const float*)d_in[5];
    float* out = (float*)d_out;

    void *Xh, *Wth, *OWth, *QKVh, *ENCh;
    cudaGetSymbolAddress(&Xh,   g_Xh);
    cudaGetSymbolAddress(&Wth,  g_Wth);
    cudaGetSymbolAddress(&OWth, g_OWth);
    cudaGetSymbolAddress(&QKVh, g_QKVh);
    cudaGetSymbolAddress(&ENCh, g_ENCh);

    // fused prep: conv_x + pack_wt + pack_owt + ts table (one launch)
    prep_all<<<57345, 256>>>(x, qw, kvw, ow);

    cudaFuncSetAttribute(hgemm<__half>, cudaFuncAttributeMaxDynamicSharedMemorySize, HGEMM_SMEM);
    cudaFuncSetAttribute(hgemm<float>,  cudaFuncAttributeMaxDynamicSharedMemorySize, HGEMM_SMEM);
    cudaFuncSetAttribute(attn_kernel,   cudaFuncAttributeMaxDynamicSharedMemorySize, ATTN_SMEM);

    // qkv = x @ Wt^T -> fp16  (M=4096, N=8192, K=3584)
    hgemm<__half><<<dim3(8192 / 128, 4096 / 128), 256, HGEMM_SMEM>>>(
        (const __half*)Xh, (const __half*)Wth, (__half*)QKVh, 8192, 3584);

    // RoPE + q scaling in place (fp16, table-based timescales)
    rope_kernel<<<dim3(4096, 24), 128>>>(segpos);

    // fp16 flash attention -> ENCh (heavy-first tile order)
    attn_kernel<<<dim3(16, 16, 2), 256, ATTN_SMEM>>>();

    // out = ENC @ OWt^T -> fp32  (M=4096, N=3584, K=4096)
    hgemm<float><<<dim3(3584 / 128, 4096 / 128), 256, HGEMM_SMEM>>>(
        (const __half*)ENCh, (const __half*)OWth, out, 3584, 4096);
}